// round 4
// baseline (speedup 1.0000x reference)
#include <cuda_runtime.h>
#include <cstddef>

// ---------------------------------------------------------------------------
// MSGMS loss, 4-scale pyramid, B=16, 512->64.
// Design:
//   - RGB->gray on the fly in scale-0 (reads the 100MB inputs exactly once)
//   - 2x2 avg-pool fused into each GMS kernel epilogue (tile-local)
//   - median3x3 via column-sort + sliding-window merge (Smith's identity)
//   - Prewitt via sliding column sums (vs/dd), fused gmap + block sum
//   - deterministic: per-block partials -> single-block finalize reduction
//   launches: gms0, gms1, gms2, gms3, finalize   (5 total)
// ---------------------------------------------------------------------------

#define TX 32
#define TY 32
#define GMS_C 0.0026f

#define N1 ((size_t)16 * 256 * 256)
#define N2 ((size_t)16 * 128 * 128)
#define N3 ((size_t)16 * 64 * 64)

__device__ float g_scratch[2 * (N1 + N2 + N3)];

// per-block partial sums: scale0 4096, scale1 1024, scale2 256, scale3 64
#define P0 0
#define P1 4096
#define P2 (4096 + 1024)
#define P3 (4096 + 1024 + 256)
#define PTOT (4096 + 1024 + 256 + 64)
__device__ float g_partial[PTOT];

#define OFF_I1 ((size_t)0)
#define OFF_R1 (OFF_I1 + N1)
#define OFF_I2 (OFF_R1 + N1)
#define OFF_R2 (OFF_I2 + N2)
#define OFF_I3 (OFF_R2 + N2)
#define OFF_R3 (OFF_I3 + N3)

__device__ __forceinline__ void mnmx(float& a, float& b) {
    float t = fminf(a, b);
    b = fmaxf(a, b);
    a = t;
}

__device__ __forceinline__ void sort3(float a, float b, float c,
                                      float& lo, float& md, float& hi) {
    mnmx(a, b); mnmx(b, c); mnmx(a, b);
    lo = a; md = b; hi = c;
}

__device__ __forceinline__ float med3(float a, float b, float c) {
    return fmaxf(fminf(a, b), fminf(fmaxf(a, b), c));
}

// Fused GMS (+ optional pooled-gray emit) kernel.
// FROM_RGB=true : srcI/srcR are [B,3,H,W] fp32; gray computed on the fly.
// FROM_RGB=false: gray read from g_scratch[srcOff*].
// WRITE_POOL=true: each block writes its 16x16 pooled gray patch.
template <bool FROM_RGB, bool WRITE_POOL>
__global__ void __launch_bounds__(256)
gms_kernel(const float* __restrict__ srcI, const float* __restrict__ srcR,
           size_t srcOffI, size_t srcOffR,
           size_t poolOffI, size_t poolOffR,
           int H, int W, int partialBase) {
    __shared__ float sGI[TY + 4][TX + 5];  // gray tile rows i0-1..i0+34
    __shared__ float sGR[TY + 4][TX + 5];
    __shared__ float sMI[TY + 2][TX + 3];  // median tile, rows i0..i0+33
    __shared__ float sMR[TY + 2][TX + 3];
    __shared__ float warpsum[8];

    const int b = blockIdx.z;
    const int i0 = blockIdx.y * TY;
    const int j0 = blockIdx.x * TX;
    const int tid = threadIdx.y * 32 + threadIdx.x;
    const size_t HW = (size_t)H * W;

    // ---- load gray tile (zero-padded halo: gray rows i0-1..i0+34) ----
    for (int idx = tid; idx < (TY + 4) * (TX + 4); idx += 256) {
        int r = idx / (TX + 4);
        int c = idx % (TX + 4);
        int gr = i0 - 1 + r;
        int gc = j0 - 1 + c;
        float vI = 0.f, vR = 0.f;
        if (gr >= 0 && gr < H && gc >= 0 && gc < W) {
            if (FROM_RGB) {
                const float* pI = srcI + (size_t)b * 3 * HW + (size_t)gr * W + gc;
                const float* pR = srcR + (size_t)b * 3 * HW + (size_t)gr * W + gc;
                vI = (pI[0] + pI[HW] + pI[2 * HW]) * (1.f / 3.f);
                vR = (pR[0] + pR[HW] + pR[2 * HW]) * (1.f / 3.f);
            } else {
                size_t o = (size_t)b * HW + (size_t)gr * W + gc;
                vI = g_scratch[srcOffI + o];
                vR = g_scratch[srcOffR + o];
            }
        }
        sGI[r][c] = vI;
        sGR[r][c] = vR;
    }
    __syncthreads();

    // ---- fused 2x2 avg-pool of the interior tile (gray rows i0..i0+31) ----
    if (WRITE_POOL) {
        int pr = tid >> 4;
        int pc = tid & 15;
        int sr = 1 + 2 * pr;
        int sc = 1 + 2 * pc;
        float pI = (sGI[sr][sc] + sGI[sr][sc + 1] +
                    sGI[sr + 1][sc] + sGI[sr + 1][sc + 1]) * 0.25f;
        float pR = (sGR[sr][sc] + sGR[sr][sc + 1] +
                    sGR[sr + 1][sc] + sGR[sr + 1][sc + 1]) * 0.25f;
        int Wp = W >> 1;
        size_t o = ((size_t)b * (H >> 1) + (i0 >> 1) + pr) * Wp + (j0 >> 1) + pc;
        g_scratch[poolOffI + o] = pI;
        g_scratch[poolOffR + o] = pR;
    }

    // ---- median stage: column-sort + sliding merge ----
    // region: rows 0..33, cols 0..33 (median at gray (i0+row, j0+col)).
    // tasks: 2 images x 34 rows x 4 runs (lens 9,9,8,8) = 272 over 256 threads
    {
        const int starts[4] = {0, 9, 18, 26};
        const int lens[4] = {9, 9, 8, 8};
        for (int task = tid; task < 272; task += 256) {
            int img = task >= 136;
            int t = task - (img ? 136 : 0);
            int row = t >> 2;
            int run = t & 3;
            int c0 = starts[run];
            int len = lens[run];
            float (*sG)[TX + 5] = img ? sGR : sGI;
            float (*sM)[TX + 3] = img ? sMR : sMI;
            float l0, m0, h0, l1, m1, h1, l2, m2, h2;
            sort3(sG[row][c0],     sG[row + 1][c0],     sG[row + 2][c0],
                  l0, m0, h0);
            sort3(sG[row][c0 + 1], sG[row + 1][c0 + 1], sG[row + 2][c0 + 1],
                  l1, m1, h1);
            for (int j = 0; j < len; ++j) {
                int c = c0 + j + 2;
                sort3(sG[row][c], sG[row + 1][c], sG[row + 2][c], l2, m2, h2);
                float mx = fmaxf(l0, fmaxf(l1, l2));
                float mn = fminf(h0, fminf(h1, h2));
                float md = med3(m0, m1, m2);
                sM[row][c0 + j] = med3(mx, md, mn);
                l0 = l1; m0 = m1; h0 = h1;
                l1 = l2; m1 = m2; h1 = h2;
            }
        }
    }
    __syncthreads();

    // ---- Prewitt (VALID) + gmap, sliding column sums ----
    // tasks: 32 rows x 4 runs of 8 = 128 (threads 128..255 idle here)
    const int Ho = H - 2, Wo = W - 2;
    float lsum = 0.f;
    if (tid < 128) {
        int row = tid >> 2;
        int tx0 = (tid & 3) * 8;
        int oy = i0 + row;
        if (oy < Ho) {
#define COLSUMS(sm, c, vs, dd)                                              \
            {                                                               \
                float _a = sm[row][c], _b = sm[row + 1][c],                 \
                      _c = sm[row + 2][c];                                  \
                vs = _a + _b + _c;                                          \
                dd = _a - _c;                                               \
            }
            float vsI0, vsI1, vsI2, ddI0, ddI1, ddI2;
            float vsR0, vsR1, vsR2, ddR0, ddR1, ddR2;
            COLSUMS(sMI, tx0,     vsI0, ddI0);
            COLSUMS(sMI, tx0 + 1, vsI1, ddI1);
            COLSUMS(sMR, tx0,     vsR0, ddR0);
            COLSUMS(sMR, tx0 + 1, vsR1, ddR1);
#pragma unroll
            for (int j = 0; j < 8; ++j) {
                COLSUMS(sMI, tx0 + j + 2, vsI2, ddI2);
                COLSUMS(sMR, tx0 + j + 2, vsR2, ddR2);
                int ox = j0 + tx0 + j;
                if (ox < Wo) {
                    float gx = (vsI2 - vsI0) * (1.f / 3.f);
                    float gy = (ddI0 + ddI1 + ddI2) * (1.f / 3.f);
                    float sI = gx * gx + gy * gy;
                    float hx = (vsR2 - vsR0) * (1.f / 3.f);
                    float hy = (ddR0 + ddR1 + ddR2) * (1.f / 3.f);
                    float sR = hx * hx + hy * hy;
                    // gI*gR = sqrt(sI*sR): one sqrt instead of two
                    float prod = sqrtf(sI * sR);
                    lsum += 1.f - __fdividef(2.f * prod + GMS_C,
                                             sI + sR + GMS_C);
                }
                vsI0 = vsI1; ddI0 = ddI1; vsI1 = vsI2; ddI1 = ddI2;
                vsR0 = vsR1; ddR0 = ddR1; vsR1 = vsR2; ddR1 = ddR2;
            }
#undef COLSUMS
        }
    }

    // ---- block reduction -> one partial-sum slot per block (deterministic) ----
#pragma unroll
    for (int off = 16; off; off >>= 1)
        lsum += __shfl_down_sync(0xffffffffu, lsum, off);
    if ((tid & 31) == 0) warpsum[tid >> 5] = lsum;
    __syncthreads();
    if (tid < 8) {
        float v = warpsum[tid];
#pragma unroll
        for (int off = 4; off; off >>= 1)
            v += __shfl_down_sync(0xffu, v, off);
        if (tid == 0) {
            int bslot = (blockIdx.z * gridDim.y + blockIdx.y) * gridDim.x
                        + blockIdx.x;
            g_partial[partialBase + bslot] = v;
        }
    }
}

// single-block deterministic reduction of all partials -> scalar loss
__global__ void __launch_bounds__(256) finalize_kernel(float* __restrict__ out) {
    __shared__ double wsum[8];
    const int base[5] = {P0, P1, P2, P3, PTOT};
    const double norm[4] = {16.0 * 510 * 510, 16.0 * 254 * 254,
                            16.0 * 126 * 126, 16.0 * 62 * 62};
    const int tid = threadIdx.x;
    double total = 0.0;
    for (int s = 0; s < 4; ++s) {
        double acc = 0.0;
        for (int i = base[s] + tid; i < base[s + 1]; i += 256)
            acc += (double)g_partial[i];
#pragma unroll
        for (int off = 16; off; off >>= 1)
            acc += __shfl_down_sync(0xffffffffu, acc, off);
        if ((tid & 31) == 0) wsum[tid >> 5] = acc;
        __syncthreads();
        if (tid == 0) {
            double t = 0.0;
            for (int w = 0; w < 8; ++w) t += wsum[w];
            total += t / norm[s];
        }
        __syncthreads();
    }
    if (tid == 0) out[0] = (float)(0.25 * total);
}

extern "C" void kernel_launch(void* const* d_in, const int* in_sizes, int n_in,
                              void* d_out, int out_size) {
    const float* Ii = (const float*)d_in[0];
    const float* Ir = (const float*)d_in[1];
    float* out = (float*)d_out;

    dim3 blk(32, 8);

    // scale 0: RGB -> gray (on the fly), GMS, emit pooled gray256
    gms_kernel<true, true><<<dim3(16, 16, 16), blk>>>(
        Ii, Ir, 0, 0, OFF_I1, OFF_R1, 512, 512, P0);

    // scale 1: GMS on gray256, emit pooled gray128
    gms_kernel<false, true><<<dim3(8, 8, 16), blk>>>(
        nullptr, nullptr, OFF_I1, OFF_R1, OFF_I2, OFF_R2, 256, 256, P1);

    // scale 2: GMS on gray128, emit pooled gray64
    gms_kernel<false, true><<<dim3(4, 4, 16), blk>>>(
        nullptr, nullptr, OFF_I2, OFF_R2, OFF_I3, OFF_R3, 128, 128, P2);

    // scale 3: GMS on gray64, no pool
    gms_kernel<false, false><<<dim3(2, 2, 16), blk>>>(
        nullptr, nullptr, OFF_I3, OFF_R3, 0, 0, 64, 64, P3);

    finalize_kernel<<<1, 256>>>(out);
}

// round 13
// speedup vs baseline: 1.1610x; 1.1610x over previous
#include <cuda_runtime.h>
#include <cstddef>

// ---------------------------------------------------------------------------
// MSGMS loss, 4-scale pyramid, B=16, 512->64.
// R13 = R6..R12 design, resubmitted for first measurement (broker starvation):
//   - gms0: RGB->gray on the fly, GMS at 512, emits gray256/128/64
//     (tile-local pool-of-pool, numerically identical to reference)
//   - gms_tail: block-specialized scales 1/2/3 (1344 independent blocks),
//     finalize fused via threadfence+counter last-block pattern
//   - median stage: 3 runs/row (single wave, ~13-step critical path)
//   - Prewitt stage: 8 runs of 4/row (256 active threads, 6-step path)
// ---------------------------------------------------------------------------

#define TX 32
#define TY 32
#define GMS_C 0.0026f

#define N1 ((size_t)16 * 256 * 256)
#define N2 ((size_t)16 * 128 * 128)
#define N3 ((size_t)16 * 64 * 64)

__device__ float g_scratch[2 * (N1 + N2 + N3)];

// per-block partial sums: scale0 4096, scale1 1024, scale2 256, scale3 64
#define P0 0
#define P1 4096
#define P2 (4096 + 1024)
#define P3 (4096 + 1024 + 256)
#define PTOT (4096 + 1024 + 256 + 64)
__device__ float g_partial[PTOT];
__device__ unsigned int g_count = 0;

#define OFF_I1 ((size_t)0)
#define OFF_R1 (OFF_I1 + N1)
#define OFF_I2 (OFF_R1 + N1)
#define OFF_R2 (OFF_I2 + N2)
#define OFF_I3 (OFF_R2 + N2)
#define OFF_R3 (OFF_I3 + N3)

#define NBLK_C (1024 + 256 + 64)

__device__ __forceinline__ void mnmx(float& a, float& b) {
    float t = fminf(a, b);
    b = fmaxf(a, b);
    a = t;
}

__device__ __forceinline__ void sort3(float a, float b, float c,
                                      float& lo, float& md, float& hi) {
    mnmx(a, b); mnmx(b, c); mnmx(a, b);
    lo = a; md = b; hi = c;
}

__device__ __forceinline__ float med3(float a, float b, float c) {
    return fmaxf(fminf(a, b), fminf(fmaxf(a, b), c));
}

// ---- shared tile pipeline pieces (operate on caller's smem arrays) --------

// median stage: sM[r][c] = median3x3 at gray (i0+r, j0+c), r,c in 0..33
// 204 tasks (2 img x 34 rows x 3 runs of len 12/11/11), single wave.
__device__ __forceinline__ void median_stage(int tid,
                                             float (*sGI)[TX + 5],
                                             float (*sGR)[TX + 5],
                                             float (*sMI)[TX + 3],
                                             float (*sMR)[TX + 3]) {
    if (tid < 204) {
        int img = tid >= 102;
        int t = tid - (img ? 102 : 0);
        int row = t / 3;
        int run = t - row * 3;
        int c0 = (run == 0) ? 0 : (run == 1 ? 12 : 23);
        int len = (run == 0) ? 12 : 11;
        float (*sG)[TX + 5] = img ? sGR : sGI;
        float (*sM)[TX + 3] = img ? sMR : sMI;
        float l0, m0, h0, l1, m1, h1, l2, m2, h2;
        sort3(sG[row][c0],     sG[row + 1][c0],     sG[row + 2][c0],
              l0, m0, h0);
        sort3(sG[row][c0 + 1], sG[row + 1][c0 + 1], sG[row + 2][c0 + 1],
              l1, m1, h1);
        for (int j = 0; j < len; ++j) {
            int c = c0 + j + 2;
            sort3(sG[row][c], sG[row + 1][c], sG[row + 2][c], l2, m2, h2);
            float mx = fmaxf(l0, fmaxf(l1, l2));
            float mn = fminf(h0, fminf(h1, h2));
            float md = med3(m0, m1, m2);
            sM[row][c0 + j] = med3(mx, md, mn);
            l0 = l1; m0 = m1; h0 = h1;
            l1 = l2; m1 = m2; h1 = h2;
        }
    }
}

// Prewitt + gmap partial sum; 256 tasks = 32 rows x 8 runs of 4, all active.
__device__ __forceinline__ float prewitt_sum(int tid, int i0, int j0,
                                             int H, int W,
                                             float (*sMI)[TX + 3],
                                             float (*sMR)[TX + 3]) {
    const int Ho = H - 2, Wo = W - 2;
    float lsum = 0.f;
    int row = tid >> 3;
    int tx0 = (tid & 7) * 4;
    int oy = i0 + row;
    if (oy < Ho) {
#define COLSUMS(sm, c, vs, dd)                                              \
        {                                                                   \
            float _a = sm[row][c], _b = sm[row + 1][c], _c = sm[row + 2][c];\
            vs = _a + _b + _c;                                              \
            dd = _a - _c;                                                   \
        }
        float vsI0, vsI1, vsI2, ddI0, ddI1, ddI2;
        float vsR0, vsR1, vsR2, ddR0, ddR1, ddR2;
        COLSUMS(sMI, tx0,     vsI0, ddI0);
        COLSUMS(sMI, tx0 + 1, vsI1, ddI1);
        COLSUMS(sMR, tx0,     vsR0, ddR0);
        COLSUMS(sMR, tx0 + 1, vsR1, ddR1);
#pragma unroll
        for (int j = 0; j < 4; ++j) {
            COLSUMS(sMI, tx0 + j + 2, vsI2, ddI2);
            COLSUMS(sMR, tx0 + j + 2, vsR2, ddR2);
            int ox = j0 + tx0 + j;
            if (ox < Wo) {
                float gx = (vsI2 - vsI0) * (1.f / 3.f);
                float gy = (ddI0 + ddI1 + ddI2) * (1.f / 3.f);
                float sI = gx * gx + gy * gy;
                float hx = (vsR2 - vsR0) * (1.f / 3.f);
                float hy = (ddR0 + ddR1 + ddR2) * (1.f / 3.f);
                float sR = hx * hx + hy * hy;
                float prod = sqrtf(sI * sR);
                lsum += 1.f - __fdividef(2.f * prod + GMS_C,
                                         sI + sR + GMS_C);
            }
            vsI0 = vsI1; ddI0 = ddI1; vsI1 = vsI2; ddI1 = ddI2;
            vsR0 = vsR1; ddR0 = ddR1; vsR1 = vsR2; ddR1 = ddR2;
        }
#undef COLSUMS
    }
    return lsum;
}

// ---------------------------------------------------------------------------
// scale-0 kernel: RGB -> gray, GMS at 512, emit gray256/128/64 pyramids
// ---------------------------------------------------------------------------
__global__ void __launch_bounds__(256)
gms0_kernel(const float* __restrict__ srcI, const float* __restrict__ srcR) {
    __shared__ float sGI[TY + 4][TX + 5];
    __shared__ float sGR[TY + 4][TX + 5];
    __shared__ float sMI[TY + 2][TX + 3];
    __shared__ float sMR[TY + 2][TX + 3];
    __shared__ float sP1I[16][17], sP1R[16][17];
    __shared__ float sP2I[8][9],  sP2R[8][9];
    __shared__ float warpsum[8];

    const int b = blockIdx.z;
    const int i0 = blockIdx.y * TY;
    const int j0 = blockIdx.x * TX;
    const int tid = threadIdx.y * 32 + threadIdx.x;
    const int H = 512, W = 512;
    const size_t HW = (size_t)H * W;

    // ---- load gray tile (zero-padded halo of 2), gray on the fly ----
    for (int idx = tid; idx < (TY + 4) * (TX + 4); idx += 256) {
        int r = idx / (TX + 4);
        int c = idx % (TX + 4);
        int gr = i0 - 1 + r;
        int gc = j0 - 1 + c;
        float vI = 0.f, vR = 0.f;
        if (gr >= 0 && gr < H && gc >= 0 && gc < W) {
            const float* pI = srcI + (size_t)b * 3 * HW + (size_t)gr * W + gc;
            const float* pR = srcR + (size_t)b * 3 * HW + (size_t)gr * W + gc;
            vI = (pI[0] + pI[HW] + pI[2 * HW]) * (1.f / 3.f);
            vR = (pR[0] + pR[HW] + pR[2 * HW]) * (1.f / 3.f);
        }
        sGI[r][c] = vI;
        sGR[r][c] = vR;
    }
    __syncthreads();

    // ---- pool level 1 (gray256): 256 threads, one output each ----
    {
        int pr = tid >> 4;
        int pc = tid & 15;
        int sr = 1 + 2 * pr;
        int sc = 1 + 2 * pc;
        float pI = (sGI[sr][sc] + sGI[sr][sc + 1] +
                    sGI[sr + 1][sc] + sGI[sr + 1][sc + 1]) * 0.25f;
        float pR = (sGR[sr][sc] + sGR[sr][sc + 1] +
                    sGR[sr + 1][sc] + sGR[sr + 1][sc + 1]) * 0.25f;
        sP1I[pr][pc] = pI;
        sP1R[pr][pc] = pR;
        size_t o = ((size_t)b * 256 + (i0 >> 1) + pr) * 256 + (j0 >> 1) + pc;
        g_scratch[OFF_I1 + o] = pI;
        g_scratch[OFF_R1 + o] = pR;
    }

    // ---- median stage (reads sGI/sGR only; overlaps with sP1 writes) ----
    median_stage(tid, sGI, sGR, sMI, sMR);
    __syncthreads();  // covers sM* AND sP1*

    // ---- pool level 2 (gray128): threads 0..63 ----
    if (tid < 64) {
        int qr = tid >> 3;
        int qc = tid & 7;
        float pI = (sP1I[2 * qr][2 * qc]     + sP1I[2 * qr][2 * qc + 1] +
                    sP1I[2 * qr + 1][2 * qc] + sP1I[2 * qr + 1][2 * qc + 1]) * 0.25f;
        float pR = (sP1R[2 * qr][2 * qc]     + sP1R[2 * qr][2 * qc + 1] +
                    sP1R[2 * qr + 1][2 * qc] + sP1R[2 * qr + 1][2 * qc + 1]) * 0.25f;
        sP2I[qr][qc] = pI;
        sP2R[qr][qc] = pR;
        size_t o = ((size_t)b * 128 + (i0 >> 2) + qr) * 128 + (j0 >> 2) + qc;
        g_scratch[OFF_I2 + o] = pI;
        g_scratch[OFF_R2 + o] = pR;
    }

    // ---- Prewitt + gmap ----
    float lsum = prewitt_sum(tid, i0, j0, H, W, sMI, sMR);

    // ---- block reduction ----
#pragma unroll
    for (int off = 16; off; off >>= 1)
        lsum += __shfl_down_sync(0xffffffffu, lsum, off);
    if ((tid & 31) == 0) warpsum[tid >> 5] = lsum;
    __syncthreads();  // covers warpsum AND sP2*

    // ---- pool level 3 (gray64): threads 32..47 (warp 1, off reduce path) ----
    if (tid >= 32 && tid < 48) {
        int t = tid - 32;
        int rr = t >> 2;
        int rc = t & 3;
        float pI = (sP2I[2 * rr][2 * rc]     + sP2I[2 * rr][2 * rc + 1] +
                    sP2I[2 * rr + 1][2 * rc] + sP2I[2 * rr + 1][2 * rc + 1]) * 0.25f;
        float pR = (sP2R[2 * rr][2 * rc]     + sP2R[2 * rr][2 * rc + 1] +
                    sP2R[2 * rr + 1][2 * rc] + sP2R[2 * rr + 1][2 * rc + 1]) * 0.25f;
        size_t o = ((size_t)b * 64 + (i0 >> 3) + rr) * 64 + (j0 >> 3) + rc;
        g_scratch[OFF_I3 + o] = pI;
        g_scratch[OFF_R3 + o] = pR;
    }

    if (tid < 8) {
        float v = warpsum[tid];
#pragma unroll
        for (int off = 4; off; off >>= 1)
            v += __shfl_down_sync(0xffu, v, off);
        if (tid == 0) {
            int bslot = (blockIdx.z * gridDim.y + blockIdx.y) * gridDim.x
                        + blockIdx.x;
            g_partial[P0 + bslot] = v;
        }
    }
}

// ---------------------------------------------------------------------------
// combined kernel: scales 1/2/3 block-specialized + fused finalize
// blocks [0,1024): scale1 (256^2), [1024,1280): scale2 (128^2),
// [1280,1344): scale3 (64^2)
// ---------------------------------------------------------------------------
__global__ void __launch_bounds__(256)
gms_tail_kernel(float* __restrict__ out) {
    __shared__ float sGI[TY + 4][TX + 5];
    __shared__ float sGR[TY + 4][TX + 5];
    __shared__ float sMI[TY + 2][TX + 3];
    __shared__ float sMR[TY + 2][TX + 3];
    __shared__ float warpsum[8];
    __shared__ bool isLast;
    __shared__ double wsum[8];

    const int blk = blockIdx.x;
    const int tid = threadIdx.x;

    int H, b, ti, tj, pslot;
    size_t offI, offR;
    if (blk < 1024) {
        H = 256; offI = OFF_I1; offR = OFF_R1;
        b = blk >> 6; int t = blk & 63; ti = t >> 3; tj = t & 7;
        pslot = P1 + blk;
    } else if (blk < 1280) {
        int k = blk - 1024;
        H = 128; offI = OFF_I2; offR = OFF_R2;
        b = k >> 4; int t = k & 15; ti = t >> 2; tj = t & 3;
        pslot = P2 + k;
    } else {
        int k = blk - 1280;
        H = 64; offI = OFF_I3; offR = OFF_R3;
        b = k >> 2; int t = k & 3; ti = t >> 1; tj = t & 1;
        pslot = P3 + k;
    }
    const int W = H;
    const int i0 = ti * TY;
    const int j0 = tj * TX;
    const size_t HW = (size_t)H * W;

    // ---- load gray tile (zero-padded halo of 2) ----
    for (int idx = tid; idx < (TY + 4) * (TX + 4); idx += 256) {
        int r = idx / (TX + 4);
        int c = idx % (TX + 4);
        int gr = i0 - 1 + r;
        int gc = j0 - 1 + c;
        float vI = 0.f, vR = 0.f;
        if (gr >= 0 && gr < H && gc >= 0 && gc < W) {
            size_t o = (size_t)b * HW + (size_t)gr * W + gc;
            vI = g_scratch[offI + o];
            vR = g_scratch[offR + o];
        }
        sGI[r][c] = vI;
        sGR[r][c] = vR;
    }
    __syncthreads();

    median_stage(tid, sGI, sGR, sMI, sMR);
    __syncthreads();

    float lsum = prewitt_sum(tid, i0, j0, H, W, sMI, sMR);

#pragma unroll
    for (int off = 16; off; off >>= 1)
        lsum += __shfl_down_sync(0xffffffffu, lsum, off);
    if ((tid & 31) == 0) warpsum[tid >> 5] = lsum;
    __syncthreads();
    if (tid == 0) {
        float v = 0.f;
        for (int w = 0; w < 8; ++w) v += warpsum[w];
        g_partial[pslot] = v;
        __threadfence();
        unsigned int old = atomicAdd(&g_count, 1u);
        isLast = (old == NBLK_C - 1);
    }
    __syncthreads();

    // ---- last block: deterministic finalize over all partials ----
    if (isLast) {
        const int base[5] = {P0, P1, P2, P3, PTOT};
        const double norm[4] = {16.0 * 510 * 510, 16.0 * 254 * 254,
                                16.0 * 126 * 126, 16.0 * 62 * 62};
        double total = 0.0;
        for (int s = 0; s < 4; ++s) {
            double acc = 0.0;
            for (int i = base[s] + tid; i < base[s + 1]; i += 256)
                acc += (double)g_partial[i];
#pragma unroll
            for (int off = 16; off; off >>= 1)
                acc += __shfl_down_sync(0xffffffffu, acc, off);
            if ((tid & 31) == 0) wsum[tid >> 5] = acc;
            __syncthreads();
            if (tid == 0) {
                double t = 0.0;
                for (int w = 0; w < 8; ++w) t += wsum[w];
                total += t / norm[s];
            }
            __syncthreads();
        }
        if (tid == 0) {
            out[0] = (float)(0.25 * total);
            g_count = 0;  // self-reset for next graph replay
        }
    }
}

extern "C" void kernel_launch(void* const* d_in, const int* in_sizes, int n_in,
                              void* d_out, int out_size) {
    const float* Ii = (const float*)d_in[0];
    const float* Ir = (const float*)d_in[1];
    float* out = (float*)d_out;

    // scale 0: RGB -> gray, GMS at 512, emit full gray pyramid
    gms0_kernel<<<dim3(16, 16, 16), dim3(32, 8)>>>(Ii, Ir);

    // scales 1/2/3 + finalize, all in one launch
    gms_tail_kernel<<<NBLK_C, 256>>>(out);
}